// round 13
// baseline (speedup 1.0000x reference)
#include <cuda_runtime.h>
#include <cstdint>

#define CCH 32
#define HH 224
#define WW 224
#define BB 16
#define KELEMS (CCH*9)
#define HWSZ (HH*WW)

// ---------------- device scratch ----------------
__device__ signed char g_w1b[9*CCH*CCH];          // conv1 weights int8 [pos][co][ci]
__device__ signed char g_u2[16*CCH*CCH];          // conv2 wino U [(tu*32+co)*32+ci]
__device__ int   g_c2corr[CCH*16];                // 32*sum_ci U  [co*16+tu]
__device__ float g_lut1_t0[CCH], g_lut1_d[CCH];
__device__ int   g_lut2_t0[CCH], g_lut2_d[CCH];   // pre-multiplied by 4
__device__ unsigned int g_xt[(size_t)BB*HH*WW*24]; // conv1 digits, q=rint(x*2^20)
__device__ unsigned int g_mid[(size_t)BB*(CCH/4)*HH*WW];

#define LDSM4(r0,r1,r2,r3,addr)                                              \
    asm volatile("ldmatrix.sync.aligned.m8n8.x4.shared.b16 {%0,%1,%2,%3}, [%4];" \
        : "=r"(r0), "=r"(r1), "=r"(r2), "=r"(r3) : "r"(addr))

#define MMA_S8(c0,c1,c2,c3,a0,a1,a2,a3,b0,b1)                                \
    asm("mma.sync.aligned.m16n8k32.row.col.s32.s8.s8.s32 "                   \
        "{%0,%1,%2,%3}, {%4,%5,%6,%7}, {%8,%9}, {%0,%1,%2,%3};"              \
        : "+r"(c0), "+r"(c1), "+r"(c2), "+r"(c3)                             \
        : "r"(a0), "r"(a1), "r"(a2), "r"(a3), "r"(b0), "r"(b1))

// ---------------------------------------------------------------------------
__global__ void setup_kernel(const float* __restrict__ conv1_w,
                             const float* __restrict__ conv2_w,
                             const float* __restrict__ bn1_w, const float* __restrict__ bn1_b,
                             const float* __restrict__ bn1_m, const float* __restrict__ bn1_v,
                             const float* __restrict__ bn2_w, const float* __restrict__ bn2_b,
                             const float* __restrict__ bn2_m, const float* __restrict__ bn2_v,
                             const float* __restrict__ a1p, const float* __restrict__ a2p,
                             const float* __restrict__ nsp) {
    __shared__ float red[KELEMS];
    __shared__ float mean1s, mean2s;
    __shared__ int   ssm1[KELEMS], ssm2[KELEMS];
    __shared__ int   Us[CCH][16];
    int co = blockIdx.x;
    int t  = threadIdx.x;           // 288

    float v1 = conv1_w[co*KELEMS + t];
    float v2 = conv2_w[co*KELEMS + t];

    red[t] = v1; __syncthreads();
    if (t < 32) red[t] += red[t + 256];
    __syncthreads();
    for (int s = 128; s > 0; s >>= 1) { if (t < s) red[t] += red[t + s]; __syncthreads(); }
    if (t == 0) mean1s = red[0] * (1.f / 288.f);
    __syncthreads();
    float m1 = mean1s;
    __syncthreads();

    red[t] = v2; __syncthreads();
    if (t < 32) red[t] += red[t + 256];
    __syncthreads();
    for (int s = 128; s > 0; s >>= 1) { if (t < s) red[t] += red[t + s]; __syncthreads(); }
    if (t == 0) mean2s = red[0] * (1.f / 288.f);
    __syncthreads();
    float m2 = mean2s;

    float d1 = v1 - m1;
    ssm1[t] = (d1 > 0.f) ? 1 : ((d1 < 0.f) ? -1 : 0);
    float d2 = v2 - m2;
    ssm2[t] = (d2 > 0.f) ? 1 : ((d2 < 0.f) ? -1 : 0);
    __syncthreads();

    int ci = t / 9, k = t % 9;
    g_w1b[(k*CCH + co)*CCH + ci] = (signed char)ssm1[t];

    if (t < CCH) {   // ci = t: conv2 Winograd U = (2G) w (2G)^T, |U|<=9
        int w3[3][3];
        #pragma unroll
        for (int kh = 0; kh < 3; kh++)
            #pragma unroll
            for (int kw = 0; kw < 3; kw++)
                w3[kh][kw] = ssm2[t*9 + kh*3 + kw];
        int T[4][3];
        #pragma unroll
        for (int j = 0; j < 3; j++) {
            T[0][j] = 2*w3[0][j];
            T[1][j] = w3[0][j] + w3[1][j] + w3[2][j];
            T[2][j] = w3[0][j] - w3[1][j] + w3[2][j];
            T[3][j] = 2*w3[2][j];
        }
        #pragma unroll
        for (int r = 0; r < 4; r++) {
            int u0 = 2*T[r][0];
            int u1 = T[r][0] + T[r][1] + T[r][2];
            int u2 = T[r][0] - T[r][1] + T[r][2];
            int u3 = 2*T[r][2];
            g_u2[((r*4+0)*CCH + co)*CCH + t] = (signed char)u0;
            g_u2[((r*4+1)*CCH + co)*CCH + t] = (signed char)u1;
            g_u2[((r*4+2)*CCH + co)*CCH + t] = (signed char)u2;
            g_u2[((r*4+3)*CCH + co)*CCH + t] = (signed char)u3;
            Us[t][r*4+0] = u0; Us[t][r*4+1] = u1;
            Us[t][r*4+2] = u2; Us[t][r*4+3] = u3;
        }
    }
    __syncthreads();
    if (t < 16) {
        int s = 0;
        #pragma unroll
        for (int c2 = 0; c2 < CCH; c2++) s += Us[c2][t];
        g_c2corr[co*16 + t] = 32 * s;
    }

    if (t == 0) {
        float a1 = *a1p, a2 = *a2p, ns = *nsp;
        {
            float std = sqrtf(bn1_v[co] + 1e-5f);
            float w = bn1_w[co] / std;
            float b = bn1_b[co] - w * bn1_m[co];
            float den = a1 * w;
            float t0 = rintf((0.5f * a2 - b) / den);
            float t1 = rintf((1.5f * a2 - b) / den);
            g_lut1_t0[co] = t0;
            g_lut1_d[co]  = t1 - t0;
        }
        {
            float std = sqrtf(bn2_v[co] + 1e-5f);
            float w = bn2_w[co] / std;
            float b = bn2_b[co] - w * bn2_m[co];
            float den = a2 * w;
            float t0 = rintf((0.5f * ns - b) / den);
            float t1 = rintf((1.5f * ns - b) / den);
            g_lut2_t0[co] = 4 * (int)t0;          // Winograd 4x scale
            g_lut2_d[co]  = 4 * (int)(t1 - t0);
        }
    }
}

// ---------------------------------------------------------------------------
// Pre-pass (R9): q = rint(x*2^20), 3 signed digits per ci
// ---------------------------------------------------------------------------
__global__ void __launch_bounds__(256)
prepass_kernel(const float* __restrict__ x) {
    __shared__ signed char stage[WW*100];
    int n = blockIdx.y, h = blockIdx.x;
    int tid = threadIdx.x;
    for (int idx = tid; idx < CCH*WW; idx += 256) {
        int ci = idx / WW, w = idx % WW;
        float v = x[(((size_t)n*CCH + ci)*HH + h)*WW + w];
        int q = __float2int_rn(v * 1048576.f);
        int b0 = (int)(signed char)(q & 0xFF);
        int q1 = (q - b0) >> 8;
        int b1 = (int)(signed char)(q1 & 0xFF);
        int b2 = (q1 - b1) >> 8;
        stage[w*100 +  0 + ci] = (signed char)b0;
        stage[w*100 + 32 + ci] = (signed char)b1;
        stage[w*100 + 64 + ci] = (signed char)b2;
    }
    __syncthreads();
    const unsigned* sw = (const unsigned*)stage;
    unsigned* dst = g_xt + ((size_t)n*HH + h)*WW*24;
    for (int idx = tid; idx < WW*24; idx += 256) {
        int w = idx / 24, c = idx % 24;
        dst[idx] = sw[w*25 + c];
    }
}

// ---------------------------------------------------------------------------
// Conv1 (R9 verbatim): raw IMMA, 3 digit planes, shared B-frags. Exact.
// ---------------------------------------------------------------------------
#define PSTR8 112
#define WSTR8 48
#define P_BYTES (180*PSTR8)
#define W_BYTES (288*WSTR8)
#define SMEM1_TOT (P_BYTES + W_BYTES)

__global__ void __launch_bounds__(256)
conv1_imma_kernel() {
    extern __shared__ __align__(16) char smem[];
    signed char* P  = (signed char*)smem;
    unsigned* P32 = (unsigned*)P;
    unsigned* W32 = (unsigned*)(smem + P_BYTES);

    int tid = threadIdx.x;
    int wid = tid >> 5, lid = tid & 31;
    int n  = blockIdx.z;
    int h0 = blockIdx.y * 8;
    int w0 = blockIdx.x * 16;

    for (int idx = tid; idx < 288*8; idx += 256) {
        int row = idx >> 3, c = idx & 7;
        W32[row*12 + c] = ((const unsigned*)g_w1b)[idx];
    }
    for (int idx = tid; idx < 180*24; idx += 256) {
        int slot = idx / 24, c = idx % 24;
        int ph = slot / 18, pw = slot % 18;
        int gh = h0 - 1 + ph, gw = w0 - 1 + pw;
        bool ok = (gh >= 0 && gh < HH && gw >= 0 && gw < WW);
        const unsigned* src = g_xt + (((size_t)n*HH + (ok ? gh : 0))*WW + (ok ? gw : 0))*24;
        P32[slot*28 + c] = ok ? src[c] : 0u;
    }
    __syncthreads();

    unsigned Pb = (unsigned)__cvta_generic_to_shared(P);
    unsigned Wb = (unsigned)__cvta_generic_to_shared(smem + P_BYTES);

    int c[3][4][4];
    #pragma unroll
    for (int p = 0; p < 3; p++)
        #pragma unroll
        for (int t = 0; t < 4; t++)
            #pragma unroll
            for (int i = 0; i < 4; i++) c[p][t][i] = 0;

    int oh = wid;
    int apix  = (lid < 16) ? lid : (lid - 16);
    int akadd = (lid < 16) ? 0 : 16;
    int bco   = ((lid >> 4) << 3) + (lid & 7);
    int bkadd = ((lid >> 3) & 1) * 16;

    #pragma unroll 3
    for (int pos = 0; pos < 9; pos++) {
        int kh = pos / 3, kw = pos % 3;
        unsigned aaddr = Pb + (unsigned)(((oh + kh)*18 + kw + apix)*PSTR8 + akadd);
        unsigned baddr = Wb + (unsigned)((pos*32 + bco)*WSTR8 + bkadd);
        unsigned b0, b1, b2, b3, b4, b5, b6, b7;
        LDSM4(b0, b1, b2, b3, baddr);
        LDSM4(b4, b5, b6, b7, baddr + 16*WSTR8);
        #pragma unroll
        for (int p = 0; p < 3; p++) {
            unsigned a0, a1, a2, a3;
            LDSM4(a0, a1, a2, a3, aaddr + p*32);
            MMA_S8(c[p][0][0], c[p][0][1], c[p][0][2], c[p][0][3], a0, a1, a2, a3, b0, b1);
            MMA_S8(c[p][1][0], c[p][1][1], c[p][1][2], c[p][1][3], a0, a1, a2, a3, b2, b3);
            MMA_S8(c[p][2][0], c[p][2][1], c[p][2][2], c[p][2][3], a0, a1, a2, a3, b4, b5);
            MMA_S8(c[p][3][0], c[p][3][1], c[p][3][2], c[p][3][3], a0, a1, a2, a3, b6, b7);
        }
    }

    int gh  = h0 + oh;
    int row = lid >> 2;
    int colq = lid & 3;
    #pragma unroll
    for (int t = 0; t < 4; t++) {
        int co0 = 8*t + 2*colq;
        long long T0a = (long long)g_lut1_t0[co0],   Da = (long long)g_lut1_d[co0];
        long long T0b = (long long)g_lut1_t0[co0+1], Db = (long long)g_lut1_d[co0+1];
        unsigned half[2];
        #pragma unroll
        for (int rpair = 0; rpair < 2; rpair++) {
            int i0 = rpair*2, i1 = rpair*2 + 1;
            long long S0 = (long long)(c[0][t][i0] + (c[1][t][i0] << 8))
                         + ((long long)c[2][t][i0] << 16);
            long long S1 = (long long)(c[0][t][i1] + (c[1][t][i1] << 8))
                         + ((long long)c[2][t][i1] << 16);
            int l0 = 0, l1 = 0;
            #pragma unroll
            for (int jj = 0; jj < 7; jj++) {
                long long tha = (T0a + (long long)jj * Da) << 20;
                long long thb = (T0b + (long long)jj * Db) << 20;
                l0 += (jj & 1) ? (S0 >= tha) : (S0 > tha);
                l1 += (jj & 1) ? (S1 >= thb) : (S1 > thb);
            }
            half[rpair] = (unsigned)l0 | ((unsigned)l1 << 8);
        }
        unsigned pA = __shfl_xor_sync(0xFFFFFFFFu, half[0], 1);
        unsigned pB = __shfl_xor_sync(0xFFFFFFFFu, half[1], 1);
        if (!(lid & 1)) {
            int cig = 2*t + (colq >> 1);
            size_t base = (((size_t)n*(CCH/4) + cig)*HH + gh)*WW + w0;
            g_mid[base + row]     = half[0] | (pA << 16);
            g_mid[base + row + 8] = half[1] | (pB << 16);
        }
    }
}

// ---------------------------------------------------------------------------
// Conv2 via exact integer Winograd F(2x2,3x3) on level data (no quantization).
// CTA 256 thr, output tile 8h x 16w = 32 wtiles. SWAR transform (bias +32),
// one s8 MMA per (tu, Mh, ntile). Y = 4*conv2; thresholds pre-x4. Exact.
// ---------------------------------------------------------------------------
#define A2STR 48
#define A2_BYTES (512*48)              // 24576
#define U2_OFF  A2_BYTES               // U: 512 rows x 48B -> 49152
#define SMSTR 545
#define LB_OFF  (32*SMSTR*4)           // 69760 (Sm ends 69752)
#define CORR_OFF (LB_OFF + 4096)       // 73856
#define SMEMW2  (CORR_OFF + 2048)      // 75904

__global__ void __launch_bounds__(256, 2)
conv2_wino_kernel(float* __restrict__ out) {
    extern __shared__ __align__(16) char smem[];
    signed char* Asm = (signed char*)smem;
    unsigned* U32 = (unsigned*)(smem + U2_OFF);
    int* corrSm = (int*)(smem + CORR_OFF);

    int tid = threadIdx.x;
    int wid = tid >> 5, lid = tid & 31;
    int n  = blockIdx.z;
    int h0 = blockIdx.y * 8;
    int w0 = blockIdx.x * 16;

    for (int idx = tid; idx < 512*8; idx += 256) {
        int row = idx >> 3, c = idx & 7;
        U32[row*12 + c] = ((const unsigned*)g_u2)[idx];
    }
    for (int idx = tid; idx < 512; idx += 256) corrSm[idx] = g_c2corr[idx];

    // staging: thread = (cig, tile); SWAR transform of packed levels
    {
        int cig = tid >> 5, tile = tid & 31;
        int th = tile >> 3, tw = tile & 7;
        const unsigned* mp = g_mid + ((size_t)n*(CCH/4) + cig)*HWSZ;
        unsigned dw[4][4];
        #pragma unroll
        for (int i = 0; i < 4; i++) {
            int gh = h0 + 2*th - 1 + i;
            bool okh = (gh >= 0 && gh < HH);
            #pragma unroll
            for (int j = 0; j < 4; j++) {
                int gw = w0 + 2*tw - 1 + j;
                dw[i][j] = (okh && gw >= 0 && gw < WW) ? mp[(size_t)gh*WW + gw] : 0u;
            }
        }
        const unsigned B8 = 0x08080808u, B16 = 0x10101010u, B32v = 0x20202020u;
        unsigned Tw[4][4];
        #pragma unroll
        for (int j = 0; j < 4; j++) {
            Tw[0][j] = (dw[0][j] + B8) - dw[2][j];
            Tw[1][j] =  dw[1][j] + dw[2][j] + B8;
            Tw[2][j] = (dw[2][j] + B8) - dw[1][j];
            Tw[3][j] = (dw[1][j] + B8) - dw[3][j];
        }
        signed char* abase = Asm;
        #pragma unroll
        for (int r = 0; r < 4; r++) {
            unsigned Dp[4];
            Dp[0] = (Tw[r][0] + B32v) - Tw[r][2];
            Dp[1] =  Tw[r][1] + Tw[r][2] + B16;
            Dp[2] = (Tw[r][2] + B32v) - Tw[r][1];
            Dp[3] = (Tw[r][1] + B32v) - Tw[r][3];
            #pragma unroll
            for (int cc = 0; cc < 4; cc++) {
                int tu = r*4 + cc;
                *(unsigned*)(abase + (tu*32 + tile)*A2STR + cig*4) = Dp[cc];
            }
        }
    }
    __syncthreads();

    unsigned Ab = (unsigned)__cvta_generic_to_shared(Asm);
    unsigned Ub = (unsigned)__cvta_generic_to_shared(smem + U2_OFF);
    int apix  = (lid < 16) ? lid : (lid - 16);
    int akadd = (lid < 16) ? 0 : 16;
    int bco   = ((lid >> 4) << 3) + (lid & 7);
    int bkadd = ((lid >> 3) & 1) * 16;

    int S[2][2][16];
    #pragma unroll
    for (int t2 = 0; t2 < 2; t2++) {
        int tu = wid*2 + t2;
        unsigned baddr = Ub + (unsigned)((tu*32 + bco)*A2STR + bkadd);
        unsigned b0, b1, b2, b3, b4, b5, b6, b7;
        LDSM4(b0, b1, b2, b3, baddr);
        LDSM4(b4, b5, b6, b7, baddr + 16*A2STR);
        #pragma unroll
        for (int Mh = 0; Mh < 2; Mh++) {
            int* s = S[t2][Mh];
            #pragma unroll
            for (int i = 0; i < 16; i++) s[i] = 0;
            unsigned aaddr = Ab + (unsigned)((tu*32 + Mh*16 + apix)*A2STR + akadd);
            unsigned a0, a1, a2, a3;
            LDSM4(a0, a1, a2, a3, aaddr);
            MMA_S8(s[0], s[1], s[2], s[3],   a0, a1, a2, a3, b0, b1);
            MMA_S8(s[4], s[5], s[6], s[7],   a0, a1, a2, a3, b2, b3);
            MMA_S8(s[8], s[9], s[10], s[11], a0, a1, a2, a3, b4, b5);
            MMA_S8(s[12], s[13], s[14], s[15], a0, a1, a2, a3, b6, b7);
        }
    }
    __syncthreads();

    int* Sm = (int*)smem;
    #pragma unroll
    for (int t2 = 0; t2 < 2; t2++) {
        int tu = wid*2 + t2;
        #pragma unroll
        for (int Mh = 0; Mh < 2; Mh++) {
            #pragma unroll
            for (int nt = 0; nt < 4; nt++) {
                #pragma unroll
                for (int i = 0; i < 4; i++) {
                    int row = (lid >> 2) + ((i >= 2) ? 8 : 0);
                    int col = nt*8 + 2*(lid & 3) + (i & 1);
                    int tile = Mh*16 + row;
                    Sm[tile*SMSTR + col*17 + tu] = S[t2][Mh][nt*4 + i];
                }
            }
        }
    }
    __syncthreads();

    unsigned char* Lb = (unsigned char*)(smem + LB_OFF);  // [tile][px4][co32]
    #pragma unroll
    for (int k = 0; k < 4; k++) {
        int u = tid + 256*k;
        int tile = u >> 5, co = u & 31;
        const int* sp = Sm + tile*SMSTR + co*17;
        const int* cp = corrSm + co*16;
        int M[16];
        #pragma unroll
        for (int tu = 0; tu < 16; tu++) M[tu] = sp[tu] - cp[tu];
        int g0[4], g1[4];
        #pragma unroll
        for (int uu = 0; uu < 4; uu++) {
            g0[uu] = M[uu] + M[4+uu] + M[8+uu];
            g1[uu] = M[4+uu] - M[8+uu] - M[12+uu];
        }
        int Y[4];
        Y[0] = g0[0] + g0[1] + g0[2];
        Y[1] = g0[1] - g0[2] - g0[3];
        Y[2] = g1[0] + g1[1] + g1[2];
        Y[3] = g1[1] - g1[2] - g1[3];
        int IT0 = g_lut2_t0[co], ID = g_lut2_d[co];
        #pragma unroll
        for (int px = 0; px < 4; px++) {
            int lvl = 0;
            #pragma unroll
            for (int jj = 0; jj < 7; jj++) {
                int th2 = IT0 + jj * ID;
                lvl += (jj & 1) ? (Y[px] >= th2) : (Y[px] > th2);
            }
            Lb[tile*128 + px*32 + co] = (unsigned char)lvl;
        }
    }
    __syncthreads();

    float* op = out + (size_t)n*CCH*HWSZ;
    #pragma unroll
    for (int k = 0; k < 16; k++) {
        int idx = tid + 256*k;
        int wcol = idx & 15;
        int i    = (idx >> 4) & 1;
        int th   = (idx >> 5) & 3;
        int co   = idx >> 7;
        int tile = th*8 + (wcol >> 1), px = i*2 + (wcol & 1);
        int lvl = Lb[tile*128 + px*32 + co];
        int gh = h0 + 2*th + i, gw = w0 + wcol;
        op[((size_t)co*HH + gh)*WW + gw] = (float)lvl;
    }
}

// ---------------------------------------------------------------------------
extern "C" void kernel_launch(void* const* d_in, const int* in_sizes, int n_in,
                              void* d_out, int out_size) {
    const float* x       = (const float*)d_in[0];
    const float* conv1_w = (const float*)d_in[1];
    const float* conv2_w = (const float*)d_in[2];
    const float* bn1_w   = (const float*)d_in[3];
    const float* bn1_b   = (const float*)d_in[4];
    const float* bn1_m   = (const float*)d_in[5];
    const float* bn1_v   = (const float*)d_in[6];
    const float* bn2_w   = (const float*)d_in[7];
    const float* bn2_b   = (const float*)d_in[8];
    const float* bn2_m   = (const float*)d_in[9];
    const float* bn2_v   = (const float*)d_in[10];
    const float* a1      = (const float*)d_in[11];
    const float* a2      = (const float*)d_in[12];
    const float* ns      = (const float*)d_in[13];

    setup_kernel<<<CCH, KELEMS>>>(conv1_w, conv2_w,
                                  bn1_w, bn1_b, bn1_m, bn1_v,
                                  bn2_w, bn2_b, bn2_m, bn2_v,
                                  a1, a2, ns);

    dim3 pgrid(HH, BB);
    prepass_kernel<<<pgrid, 256>>>(x);

    cudaFuncSetAttribute(conv1_imma_kernel,
                         cudaFuncAttributeMaxDynamicSharedMemorySize, SMEM1_TOT);
    dim3 grid1(WW/16, HH/8, BB);
    conv1_imma_kernel<<<grid1, 256, SMEM1_TOT>>>();

    cudaFuncSetAttribute(conv2_wino_kernel,
                         cudaFuncAttributeMaxDynamicSharedMemorySize, SMEMW2);
    conv2_wino_kernel<<<grid1, 256, SMEMW2>>>((float*)d_out);
}

// round 14
// speedup vs baseline: 1.7571x; 1.7571x over previous
#include <cuda_runtime.h>
#include <cstdint>

#define CCH 32
#define HH 224
#define WW 224
#define BB 16
#define KELEMS (CCH*9)
#define HWSZ (HH*WW)

__device__ signed char g_w1b[9*CCH*CCH];
__device__ signed char g_u2[16*CCH*CCH];
__device__ int   g_c2corr[CCH*16];
__device__ float g_lut1_t0[CCH], g_lut1_d[CCH];
__device__ int   g_lut2_t0[CCH], g_lut2_d[CCH];   // pre-x4
__device__ unsigned int g_xt[(size_t)BB*HH*WW*24];
__device__ unsigned int g_mid[(size_t)BB*(CCH/4)*HH*WW];

#define LDSM4(r0,r1,r2,r3,addr)                                              \
    asm volatile("ldmatrix.sync.aligned.m8n8.x4.shared.b16 {%0,%1,%2,%3}, [%4];" \
        : "=r"(r0), "=r"(r1), "=r"(r2), "=r"(r3) : "r"(addr))

#define MMA_S8(c0,c1,c2,c3,a0,a1,a2,a3,b0,b1)                                \
    asm("mma.sync.aligned.m16n8k32.row.col.s32.s8.s8.s32 "                   \
        "{%0,%1,%2,%3}, {%4,%5,%6,%7}, {%8,%9}, {%0,%1,%2,%3};"              \
        : "+r"(c0), "+r"(c1), "+r"(c2), "+r"(c3)                             \
        : "r"(a0), "r"(a1), "r"(a2), "r"(a3), "r"(b0), "r"(b1))

// ---------------------------------------------------------------------------
__global__ void setup_kernel(const float* __restrict__ conv1_w,
                             const float* __restrict__ conv2_w,
                             const float* __restrict__ bn1_w, const float* __restrict__ bn1_b,
                             const float* __restrict__ bn1_m, const float* __restrict__ bn1_v,
                             const float* __restrict__ bn2_w, const float* __restrict__ bn2_b,
                             const float* __restrict__ bn2_m, const float* __restrict__ bn2_v,
                             const float* __restrict__ a1p, const float* __restrict__ a2p,
                             const float* __restrict__ nsp) {
    __shared__ float red[KELEMS];
    __shared__ float mean1s, mean2s;
    __shared__ int   ssm1[KELEMS], ssm2[KELEMS];
    __shared__ int   Us[CCH][16];
    int co = blockIdx.x;
    int t  = threadIdx.x;           // 288

    float v1 = conv1_w[co*KELEMS + t];
    float v2 = conv2_w[co*KELEMS + t];

    red[t] = v1; __syncthreads();
    if (t < 32) red[t] += red[t + 256];
    __syncthreads();
    for (int s = 128; s > 0; s >>= 1) { if (t < s) red[t] += red[t + s]; __syncthreads(); }
    if (t == 0) mean1s = red[0] * (1.f / 288.f);
    __syncthreads();
    float m1 = mean1s;
    __syncthreads();

    red[t] = v2; __syncthreads();
    if (t < 32) red[t] += red[t + 256];
    __syncthreads();
    for (int s = 128; s > 0; s >>= 1) { if (t < s) red[t] += red[t + s]; __syncthreads(); }
    if (t == 0) mean2s = red[0] * (1.f / 288.f);
    __syncthreads();
    float m2 = mean2s;

    float d1 = v1 - m1;
    ssm1[t] = (d1 > 0.f) ? 1 : ((d1 < 0.f) ? -1 : 0);
    float d2 = v2 - m2;
    ssm2[t] = (d2 > 0.f) ? 1 : ((d2 < 0.f) ? -1 : 0);
    __syncthreads();

    int ci = t / 9, k = t % 9;
    g_w1b[(k*CCH + co)*CCH + ci] = (signed char)ssm1[t];

    if (t < CCH) {   // ci = t: conv2 Winograd U = (2G) w (2G)^T
        int w3[3][3];
        #pragma unroll
        for (int kh = 0; kh < 3; kh++)
            #pragma unroll
            for (int kw = 0; kw < 3; kw++)
                w3[kh][kw] = ssm2[t*9 + kh*3 + kw];
        int T[4][3];
        #pragma unroll
        for (int j = 0; j < 3; j++) {
            T[0][j] = 2*w3[0][j];
            T[1][j] = w3[0][j] + w3[1][j] + w3[2][j];
            T[2][j] = w3[0][j] - w3[1][j] + w3[2][j];
            T[3][j] = 2*w3[2][j];
        }
        #pragma unroll
        for (int r = 0; r < 4; r++) {
            int u0 = 2*T[r][0];
            int u1 = T[r][0] + T[r][1] + T[r][2];
            int u2 = T[r][0] - T[r][1] + T[r][2];
            int u3 = 2*T[r][2];
            g_u2[((r*4+0)*CCH + co)*CCH + t] = (signed char)u0;
            g_u2[((r*4+1)*CCH + co)*CCH + t] = (signed char)u1;
            g_u2[((r*4+2)*CCH + co)*CCH + t] = (signed char)u2;
            g_u2[((r*4+3)*CCH + co)*CCH + t] = (signed char)u3;
            Us[t][r*4+0] = u0; Us[t][r*4+1] = u1;
            Us[t][r*4+2] = u2; Us[t][r*4+3] = u3;
        }
    }
    __syncthreads();
    if (t < 16) {
        int s = 0;
        #pragma unroll
        for (int c2 = 0; c2 < CCH; c2++) s += Us[c2][t];
        g_c2corr[co*16 + t] = 32 * s;
    }

    if (t == 0) {
        float a1 = *a1p, a2 = *a2p, ns = *nsp;
        {
            float std = sqrtf(bn1_v[co] + 1e-5f);
            float w = bn1_w[co] / std;
            float b = bn1_b[co] - w * bn1_m[co];
            float den = a1 * w;
            float t0 = rintf((0.5f * a2 - b) / den);
            float t1 = rintf((1.5f * a2 - b) / den);
            g_lut1_t0[co] = t0;
            g_lut1_d[co]  = t1 - t0;
        }
        {
            float std = sqrtf(bn2_v[co] + 1e-5f);
            float w = bn2_w[co] / std;
            float b = bn2_b[co] - w * bn2_m[co];
            float den = a2 * w;
            float t0 = rintf((0.5f * ns - b) / den);
            float t1 = rintf((1.5f * ns - b) / den);
            g_lut2_t0[co] = 4 * (int)t0;
            g_lut2_d[co]  = 4 * (int)(t1 - t0);
        }
    }
}

// ---------------------------------------------------------------------------
__global__ void __launch_bounds__(256)
prepass_kernel(const float* __restrict__ x) {
    __shared__ signed char stage[WW*100];
    int n = blockIdx.y, h = blockIdx.x;
    int tid = threadIdx.x;
    for (int idx = tid; idx < CCH*WW; idx += 256) {
        int ci = idx / WW, w = idx % WW;
        float v = x[(((size_t)n*CCH + ci)*HH + h)*WW + w];
        int q = __float2int_rn(v * 1048576.f);
        int b0 = (int)(signed char)(q & 0xFF);
        int q1 = (q - b0) >> 8;
        int b1 = (int)(signed char)(q1 & 0xFF);
        int b2 = (q1 - b1) >> 8;
        stage[w*100 +  0 + ci] = (signed char)b0;
        stage[w*100 + 32 + ci] = (signed char)b1;
        stage[w*100 + 64 + ci] = (signed char)b2;
    }
    __syncthreads();
    const unsigned* sw = (const unsigned*)stage;
    unsigned* dst = g_xt + ((size_t)n*HH + h)*WW*24;
    for (int idx = tid; idx < WW*24; idx += 256) {
        int w = idx / 24, c = idx % 24;
        dst[idx] = sw[w*25 + c];
    }
}

// ---------------------------------------------------------------------------
// Conv1: R9 verbatim (exact, validated)
// ---------------------------------------------------------------------------
#define PSTR8 112
#define WSTR8 48
#define P_BYTES (180*PSTR8)
#define W_BYTES (288*WSTR8)
#define SMEM1_TOT (P_BYTES + W_BYTES)

__global__ void __launch_bounds__(256)
conv1_imma_kernel() {
    extern __shared__ __align__(16) char smem[];
    signed char* P  = (signed char*)smem;
    unsigned* P32 = (unsigned*)P;
    unsigned* W32 = (unsigned*)(smem + P_BYTES);

    int tid = threadIdx.x;
    int wid = tid >> 5, lid = tid & 31;
    int n  = blockIdx.z;
    int h0 = blockIdx.y * 8;
    int w0 = blockIdx.x * 16;

    for (int idx = tid; idx < 288*8; idx += 256) {
        int row = idx >> 3, c = idx & 7;
        W32[row*12 + c] = ((const unsigned*)g_w1b)[idx];
    }
    for (int idx = tid; idx < 180*24; idx += 256) {
        int slot = idx / 24, c = idx % 24;
        int ph = slot / 18, pw = slot % 18;
        int gh = h0 - 1 + ph, gw = w0 - 1 + pw;
        bool ok = (gh >= 0 && gh < HH && gw >= 0 && gw < WW);
        const unsigned* src = g_xt + (((size_t)n*HH + (ok ? gh : 0))*WW + (ok ? gw : 0))*24;
        P32[slot*28 + c] = ok ? src[c] : 0u;
    }
    __syncthreads();

    unsigned Pb = (unsigned)__cvta_generic_to_shared(P);
    unsigned Wb = (unsigned)__cvta_generic_to_shared(smem + P_BYTES);

    int c[3][4][4];
    #pragma unroll
    for (int p = 0; p < 3; p++)
        #pragma unroll
        for (int t = 0; t < 4; t++)
            #pragma unroll
            for (int i = 0; i < 4; i++) c[p][t][i] = 0;

    int oh = wid;
    int apix  = (lid < 16) ? lid : (lid - 16);
    int akadd = (lid < 16) ? 0 : 16;
    int bco   = ((lid >> 4) << 3) + (lid & 7);
    int bkadd = ((lid >> 3) & 1) * 16;

    #pragma unroll 3
    for (int pos = 0; pos < 9; pos++) {
        int kh = pos / 3, kw = pos % 3;
        unsigned aaddr = Pb + (unsigned)(((oh + kh)*18 + kw + apix)*PSTR8 + akadd);
        unsigned baddr = Wb + (unsigned)((pos*32 + bco)*WSTR8 + bkadd);
        unsigned b0, b1, b2, b3, b4, b5, b6, b7;
        LDSM4(b0, b1, b2, b3, baddr);
        LDSM4(b4, b5, b6, b7, baddr + 16*WSTR8);
        #pragma unroll
        for (int p = 0; p < 3; p++) {
            unsigned a0, a1, a2, a3;
            LDSM4(a0, a1, a2, a3, aaddr + p*32);
            MMA_S8(c[p][0][0], c[p][0][1], c[p][0][2], c[p][0][3], a0, a1, a2, a3, b0, b1);
            MMA_S8(c[p][1][0], c[p][1][1], c[p][1][2], c[p][1][3], a0, a1, a2, a3, b2, b3);
            MMA_S8(c[p][2][0], c[p][2][1], c[p][2][2], c[p][2][3], a0, a1, a2, a3, b4, b5);
            MMA_S8(c[p][3][0], c[p][3][1], c[p][3][2], c[p][3][3], a0, a1, a2, a3, b6, b7);
        }
    }

    int gh  = h0 + oh;
    int row = lid >> 2;
    int colq = lid & 3;
    #pragma unroll
    for (int t = 0; t < 4; t++) {
        int co0 = 8*t + 2*colq;
        long long T0a = (long long)g_lut1_t0[co0],   Da = (long long)g_lut1_d[co0];
        long long T0b = (long long)g_lut1_t0[co0+1], Db = (long long)g_lut1_d[co0+1];
        unsigned half[2];
        #pragma unroll
        for (int rpair = 0; rpair < 2; rpair++) {
            int i0 = rpair*2, i1 = rpair*2 + 1;
            long long S0 = (long long)(c[0][t][i0] + (c[1][t][i0] << 8))
                         + ((long long)c[2][t][i0] << 16);
            long long S1 = (long long)(c[0][t][i1] + (c[1][t][i1] << 8))
                         + ((long long)c[2][t][i1] << 16);
            int l0 = 0, l1 = 0;
            #pragma unroll
            for (int jj = 0; jj < 7; jj++) {
                long long tha = (T0a + (long long)jj * Da) << 20;
                long long thb = (T0b + (long long)jj * Db) << 20;
                l0 += (jj & 1) ? (S0 >= tha) : (S0 > tha);
                l1 += (jj & 1) ? (S1 >= thb) : (S1 > thb);
            }
            half[rpair] = (unsigned)l0 | ((unsigned)l1 << 8);
        }
        unsigned pA = __shfl_xor_sync(0xFFFFFFFFu, half[0], 1);
        unsigned pB = __shfl_xor_sync(0xFFFFFFFFu, half[1], 1);
        if (!(lid & 1)) {
            int cig = 2*t + (colq >> 1);
            size_t base = (((size_t)n*(CCH/4) + cig)*HH + gh)*WW + w0;
            g_mid[base + row]     = half[0] | (pA << 16);
            g_mid[base + row + 8] = half[1] | (pB << 16);
        }
    }
}

// ---------------------------------------------------------------------------
// Conv2 wino v2: warp = (Mh, nt), all 16 tu in-warp, in-register epilogue.
// ---------------------------------------------------------------------------
#define A2STR 48
#define A2_BYTES (512*A2STR)
#define U2_OFF  A2_BYTES
#define CORR_OFF (U2_OFF + 512*A2STR)   // 49152
#define SMEMW2  (CORR_OFF + 2048)       // 51200

__global__ void __launch_bounds__(256, 2)
conv2_wino_kernel(float* __restrict__ out) {
    extern __shared__ __align__(16) char smem[];
    signed char* Asm = (signed char*)smem;
    unsigned* U32 = (unsigned*)(smem + U2_OFF);
    int* corrSm = (int*)(smem + CORR_OFF);

    int tid = threadIdx.x;
    int wid = tid >> 5, lid = tid & 31;
    int n  = blockIdx.z;
    int h0 = blockIdx.y * 8;
    int w0 = blockIdx.x * 16;

    for (int idx = tid; idx < 512*8; idx += 256) {
        int row = idx >> 3, c = idx & 7;
        U32[row*12 + c] = ((const unsigned*)g_u2)[idx];
    }
    for (int idx = tid; idx < 512; idx += 256) corrSm[idx] = g_c2corr[idx];

    {   // staging: thread = (cig, tile); SWAR transform (R13-validated)
        int cig = tid >> 5, tile = tid & 31;
        int th = tile >> 3, tw = tile & 7;
        const unsigned* mp = g_mid + ((size_t)n*(CCH/4) + cig)*HWSZ;
        unsigned dw[4][4];
        #pragma unroll
        for (int i = 0; i < 4; i++) {
            int gh = h0 + 2*th - 1 + i;
            bool okh = (gh >= 0 && gh < HH);
            #pragma unroll
            for (int j = 0; j < 4; j++) {
                int gw = w0 + 2*tw - 1 + j;
                dw[i][j] = (okh && gw >= 0 && gw < WW) ? mp[(size_t)gh*WW + gw] : 0u;
            }
        }
        const unsigned B8 = 0x08080808u, B16 = 0x10101010u, B32v = 0x20202020u;
        unsigned Tw[4][4];
        #pragma unroll
        for (int j = 0; j < 4; j++) {
            Tw[0][j] = (dw[0][j] + B8) - dw[2][j];
            Tw[1][j] =  dw[1][j] + dw[2][j] + B8;
            Tw[2][j] = (dw[2][j] + B8) - dw[1][j];
            Tw[3][j] = (dw[1][j] + B8) - dw[3][j];
        }
        #pragma unroll
        for (int r = 0; r < 4; r++) {
            unsigned Dp[4];
            Dp[0] = (Tw[r][0] + B32v) - Tw[r][2];
            Dp[1] =  Tw[r][1] + Tw[r][2] + B16;
            Dp[2] = (Tw[r][2] + B32v) - Tw[r][1];
            Dp[3] = (Tw[r][1] + B32v) - Tw[r][3];
            #pragma unroll
            for (int cc = 0; cc < 4; cc++) {
                int tu = r*4 + cc;
                *(unsigned*)(Asm + (tu*32 + tile)*A2STR + cig*4) = Dp[cc];
            }
        }
    }
    __syncthreads();

    unsigned Ab = (unsigned)__cvta_generic_to_shared(Asm);
    unsigned Ub = (unsigned)__cvta_generic_to_shared(smem + U2_OFF);
    int Mh = wid >> 2, nt = wid & 3;
    int apix  = (lid < 16) ? lid : (lid - 16);
    int akadd = (lid < 16) ? 0 : 16;
    int btu   = (lid >= 16) ? 1 : 0;
    int brow  = nt*8 + (lid & 7);
    int bkadd = ((lid >> 3) & 1) * 16;

    int S[16][4];
    #pragma unroll
    for (int tp = 0; tp < 8; tp++) {
        int tu0 = 2*tp;
        unsigned b0, b1, b2, b3;
        LDSM4(b0, b1, b2, b3, Ub + (unsigned)(((tu0 + btu)*32 + brow)*A2STR + bkadd));
        unsigned a0, a1, a2, a3;
        LDSM4(a0, a1, a2, a3, Ab + (unsigned)((tu0*32 + Mh*16 + apix)*A2STR + akadd));
        S[tu0][0] = 0; S[tu0][1] = 0; S[tu0][2] = 0; S[tu0][3] = 0;
        MMA_S8(S[tu0][0], S[tu0][1], S[tu0][2], S[tu0][3], a0, a1, a2, a3, b0, b1);
        LDSM4(a0, a1, a2, a3, Ab + (unsigned)(((tu0+1)*32 + Mh*16 + apix)*A2STR + akadd));
        S[tu0+1][0] = 0; S[tu0+1][1] = 0; S[tu0+1][2] = 0; S[tu0+1][3] = 0;
        MMA_S8(S[tu0+1][0], S[tu0+1][1], S[tu0+1][2], S[tu0+1][3], a0, a1, a2, a3, b2, b3);
    }

    // in-register epilogue: lane owns (rowLo,rowHi) x (coA,coB); 16 tu in-lane
    int rowp = lid >> 2, colq = lid & 3;
    int coA = nt*8 + 2*colq;
    float* op = out + (size_t)n*CCH*HWSZ;
    #pragma unroll
    for (int sl = 0; sl < 4; sl++) {
        int tile = Mh*16 + rowp + ((sl >= 2) ? 8 : 0);
        int co   = coA + (sl & 1);
        const int* cp = corrSm + co*16;
        int M[16];
        #pragma unroll
        for (int tu = 0; tu < 16; tu++) M[tu] = S[tu][sl] - cp[tu];
        int g0[4], g1[4];
        #pragma unroll
        for (int uu = 0; uu < 4; uu++) {
            g0[uu] = M[uu] + M[4+uu] + M[8+uu];
            g1[uu] = M[4+uu] - M[8+uu] - M[12+uu];
        }
        int Y[4];
        Y[0] = g0[0] + g0[1] + g0[2];
        Y[1] = g0[1] - g0[2] - g0[3];
        Y[2] = g1[0] + g1[1] + g1[2];
        Y[3] = g1[1] - g1[2] - g1[3];
        int IT0 = g_lut2_t0[co], ID = g_lut2_d[co];
        int th_ = tile >> 3, tw_ = tile & 7;
        #pragma unroll
        for (int px = 0; px < 4; px++) {
            int lvl = 0;
            #pragma unroll
            for (int jj = 0; jj < 7; jj++) {
                int th2 = IT0 + jj * ID;
                lvl += (jj & 1) ? (Y[px] >= th2) : (Y[px] > th2);
            }
            int gh = h0 + 2*th_ + (px >> 1);
            int gw = w0 + 2*tw_ + (px & 1);
            op[((size_t)co*HH + gh)*WW + gw] = (float)lvl;
        }
    }
}

// ---------------------------------------------------------------------------
extern "C" void kernel_launch(void* const* d_in, const int* in_sizes, int n_in,
                              void* d_out, int out_size) {
    const float* x       = (const float*)d_in[0];
    const float* conv1_w = (const float*)d_in[1];
    const float* conv2_w = (const float*)d_in[2];
    const float* bn1_w   = (const float*)d_in[3];
    const float* bn1_b   = (const float*)d_in[4];
    const float* bn1_m   = (const float*)d_in[5];
    const float* bn1_v   = (const float*)d_in[6];
    const float* bn2_w   = (const float*)d_in[7];
    const float* bn2_b   = (const float*)d_in[8];
    const float* bn2_m   = (const float*)d_in[9];
    const float* bn2_v   = (const float*)d_in[10];
    const float* a1      = (const float*)d_in[11];
    const float* a2      = (const float*)d_in[12];
    const float* ns      = (const float*)d_in[13];

    setup_kernel<<<CCH, KELEMS>>>(conv1_w, conv2_w,
                                  bn1_w, bn1_b, bn1_m, bn1_v,
                                  bn2_w, bn2_b, bn2_m, bn2_v,
                                  a1, a2, ns);

    dim3 pgrid(HH, BB);
    prepass_kernel<<<pgrid, 256>>>(x);

    cudaFuncSetAttribute(conv1_imma_kernel,
                         cudaFuncAttributeMaxDynamicSharedMemorySize, SMEM1_TOT);
    dim3 grid1(WW/16, HH/8, BB);
    conv1_imma_kernel<<<grid1, 256, SMEM1_TOT>>>();

    cudaFuncSetAttribute(conv2_wino_kernel,
                         cudaFuncAttributeMaxDynamicSharedMemorySize, SMEMW2);
    conv2_wino_kernel<<<grid1, 256, SMEMW2>>>((float*)d_out);
}

// round 16
// speedup vs baseline: 2.0338x; 1.1574x over previous
#include <cuda_runtime.h>
#include <cstdint>

#define CCH 32
#define HH 224
#define WW 224
#define BB 16
#define KELEMS (CCH*9)
#define HWSZ (HH*WW)

__device__ signed char g_u1[16*CCH*CCH];
__device__ signed char g_u2[16*CCH*CCH];
__device__ int   g_c2corr[CCH*16];
__device__ float g_lut1_t0[CCH], g_lut1_d[CCH];
__device__ int   g_lut2_t0[CCH], g_lut2_d[CCH];   // pre-x4
__device__ int   g_xt[(size_t)BB*HH*WW*32];       // q = rint(x*2^20), NHWC
__device__ unsigned int g_mid[(size_t)BB*(CCH/4)*HH*WW];

#define LDSM4(r0,r1,r2,r3,addr)                                              \
    asm volatile("ldmatrix.sync.aligned.m8n8.x4.shared.b16 {%0,%1,%2,%3}, [%4];" \
        : "=r"(r0), "=r"(r1), "=r"(r2), "=r"(r3) : "r"(addr))

#define MMA_S8(c0,c1,c2,c3,a0,a1,a2,a3,b0,b1)                                \
    asm("mma.sync.aligned.m16n8k32.row.col.s32.s8.s8.s32 "                   \
        "{%0,%1,%2,%3}, {%4,%5,%6,%7}, {%8,%9}, {%0,%1,%2,%3};"              \
        : "+r"(c0), "+r"(c1), "+r"(c2), "+r"(c3)                             \
        : "r"(a0), "r"(a1), "r"(a2), "r"(a3), "r"(b0), "r"(b1))

// ---------------------------------------------------------------------------
__global__ void setup_kernel(const float* __restrict__ conv1_w,
                             const float* __restrict__ conv2_w,
                             const float* __restrict__ bn1_w, const float* __restrict__ bn1_b,
                             const float* __restrict__ bn1_m, const float* __restrict__ bn1_v,
                             const float* __restrict__ bn2_w, const float* __restrict__ bn2_b,
                             const float* __restrict__ bn2_m, const float* __restrict__ bn2_v,
                             const float* __restrict__ a1p, const float* __restrict__ a2p,
                             const float* __restrict__ nsp) {
    __shared__ float red[KELEMS];
    __shared__ float mean1s, mean2s;
    __shared__ int   ssm1[KELEMS], ssm2[KELEMS];
    __shared__ int   Us[CCH][16];
    int co = blockIdx.x;
    int t  = threadIdx.x;           // 288

    float v1 = conv1_w[co*KELEMS + t];
    float v2 = conv2_w[co*KELEMS + t];

    red[t] = v1; __syncthreads();
    if (t < 32) red[t] += red[t + 256];
    __syncthreads();
    for (int s = 128; s > 0; s >>= 1) { if (t < s) red[t] += red[t + s]; __syncthreads(); }
    if (t == 0) mean1s = red[0] * (1.f / 288.f);
    __syncthreads();
    float m1 = mean1s;
    __syncthreads();

    red[t] = v2; __syncthreads();
    if (t < 32) red[t] += red[t + 256];
    __syncthreads();
    for (int s = 128; s > 0; s >>= 1) { if (t < s) red[t] += red[t + s]; __syncthreads(); }
    if (t == 0) mean2s = red[0] * (1.f / 288.f);
    __syncthreads();
    float m2 = mean2s;

    float d1 = v1 - m1;
    ssm1[t] = (d1 > 0.f) ? 1 : ((d1 < 0.f) ? -1 : 0);
    float d2 = v2 - m2;
    ssm2[t] = (d2 > 0.f) ? 1 : ((d2 < 0.f) ? -1 : 0);
    __syncthreads();

    if (t < CCH) {   // ci = t: Winograd U = (2G) w (2G)^T for BOTH convs
        #pragma unroll
        for (int which = 0; which < 2; which++) {
            const int* sv = which ? ssm2 : ssm1;
            signed char* gu = which ? g_u2 : g_u1;
            int w3[3][3];
            #pragma unroll
            for (int kh = 0; kh < 3; kh++)
                #pragma unroll
                for (int kw = 0; kw < 3; kw++)
                    w3[kh][kw] = sv[t*9 + kh*3 + kw];
            int T[4][3];
            #pragma unroll
            for (int j = 0; j < 3; j++) {
                T[0][j] = 2*w3[0][j];
                T[1][j] = w3[0][j] + w3[1][j] + w3[2][j];
                T[2][j] = w3[0][j] - w3[1][j] + w3[2][j];
                T[3][j] = 2*w3[2][j];
            }
            #pragma unroll
            for (int r = 0; r < 4; r++) {
                int u0 = 2*T[r][0];
                int u1 = T[r][0] + T[r][1] + T[r][2];
                int u2 = T[r][0] - T[r][1] + T[r][2];
                int u3 = 2*T[r][2];
                gu[((r*4+0)*CCH + co)*CCH + t] = (signed char)u0;
                gu[((r*4+1)*CCH + co)*CCH + t] = (signed char)u1;
                gu[((r*4+2)*CCH + co)*CCH + t] = (signed char)u2;
                gu[((r*4+3)*CCH + co)*CCH + t] = (signed char)u3;
                if (which) {
                    Us[t][r*4+0] = u0; Us[t][r*4+1] = u1;
                    Us[t][r*4+2] = u2; Us[t][r*4+3] = u3;
                }
            }
        }
    }
    __syncthreads();
    if (t < 16) {
        int s = 0;
        #pragma unroll
        for (int c2 = 0; c2 < CCH; c2++) s += Us[c2][t];
        g_c2corr[co*16 + t] = 32 * s;
    }

    if (t == 0) {
        float a1 = *a1p, a2 = *a2p, ns = *nsp;
        {
            float std = sqrtf(bn1_v[co] + 1e-5f);
            float w = bn1_w[co] / std;
            float b = bn1_b[co] - w * bn1_m[co];
            float den = a1 * w;
            float t0 = rintf((0.5f * a2 - b) / den);
            float t1 = rintf((1.5f * a2 - b) / den);
            g_lut1_t0[co] = t0;
            g_lut1_d[co]  = t1 - t0;
        }
        {
            float std = sqrtf(bn2_v[co] + 1e-5f);
            float w = bn2_w[co] / std;
            float b = bn2_b[co] - w * bn2_m[co];
            float den = a2 * w;
            float t0 = rintf((0.5f * ns - b) / den);
            float t1 = rintf((1.5f * ns - b) / den);
            g_lut2_t0[co] = 4 * (int)t0;
            g_lut2_d[co]  = 4 * (int)(t1 - t0);
        }
    }
}

// ---------------------------------------------------------------------------
__global__ void __launch_bounds__(256)
prepass_kernel(const float* __restrict__ x) {
    __shared__ int stage[WW*33];
    int n = blockIdx.y, h = blockIdx.x;
    int tid = threadIdx.x;
    for (int idx = tid; idx < CCH*WW; idx += 256) {
        int ci = idx / WW, w = idx % WW;
        float v = x[(((size_t)n*CCH + ci)*HH + h)*WW + w];
        stage[w*33 + ci] = __float2int_rn(v * 1048576.f);   // 2^20
    }
    __syncthreads();
    int* dst = g_xt + ((size_t)n*HH + h)*WW*32;
    for (int idx = tid; idx < WW*32; idx += 256) {
        int w = idx >> 5, ci = idx & 31;
        dst[idx] = stage[w*33 + ci];
    }
}

// ---------------------------------------------------------------------------
// Conv1 Winograd @2^20, 4 digit planes, two-pass (S01 then S23), in-register
// epilogue on the R14-validated fabric. Y = Y01 + Y23<<16 (exact int64).
// ---------------------------------------------------------------------------
#define A1STR 144
#define A1_BYTES (512*A1STR)            // 73728
#define U1_OFF  A1_BYTES
#define U1STR 48
#define SMEMW1  (U1_OFF + 512*U1STR)    // 98304

__device__ __forceinline__ int lut1_ll(long long Y, long long T0, long long D) {
    int lvl = 0;
    #pragma unroll
    for (int jj = 0; jj < 7; jj++) {
        long long th = (T0 + (long long)jj * D) << 22;   // 4 * 2^20
        lvl += (jj & 1) ? (Y >= th) : (Y > th);
    }
    return lvl;
}

__global__ void __launch_bounds__(256, 2)
conv1_wino_kernel() {
    extern __shared__ __align__(16) char smem[];
    signed char* Asm = (signed char*)smem;
    unsigned* U32 = (unsigned*)(smem + U1_OFF);

    int tid = threadIdx.x;
    int wid = tid >> 5, lid = tid & 31;
    int n  = blockIdx.z;
    int h0 = blockIdx.y * 8;
    int w0 = blockIdx.x * 16;

    for (int idx = tid; idx < 512*8; idx += 256) {
        int row = idx >> 3, c = idx & 7;
        U32[row*12 + c] = ((const unsigned*)g_u1)[idx];
    }

    const int* xin = g_xt + (size_t)n*HWSZ*32;
    #pragma unroll
    for (int k = 0; k < 4; k++) {
        int u = tid + 256*k;
        int tile = u >> 5, ci = u & 31;
        int th = tile >> 3, tw = tile & 7;
        int d[4][4];
        #pragma unroll
        for (int i = 0; i < 4; i++) {
            int gh = h0 + 2*th - 1 + i;
            bool okh = (gh >= 0 && gh < HH);
            int ghc = okh ? gh : 0;
            #pragma unroll
            for (int j = 0; j < 4; j++) {
                int gw = w0 + 2*tw - 1 + j;
                bool ok = okh && (gw >= 0 && gw < WW);
                int gwc = ok ? gw : 0;
                int v = xin[((size_t)ghc*WW + gwc)*32 + ci];
                d[i][j] = ok ? v : 0;
            }
        }
        int T[4][4];
        #pragma unroll
        for (int j = 0; j < 4; j++) {
            T[0][j] = d[0][j] - d[2][j];
            T[1][j] = d[1][j] + d[2][j];
            T[2][j] = d[2][j] - d[1][j];
            T[3][j] = d[1][j] - d[3][j];
        }
        #pragma unroll
        for (int i = 0; i < 4; i++) {
            int Dv[4];
            Dv[0] = T[i][0] - T[i][2];
            Dv[1] = T[i][1] + T[i][2];
            Dv[2] = T[i][2] - T[i][1];
            Dv[3] = T[i][1] - T[i][3];
            #pragma unroll
            for (int uu = 0; uu < 4; uu++) {
                int tu = i*4 + uu;
                int v = Dv[uu];
                int b0 = (int)(signed char)(v & 0xFF);
                int r1 = (v - b0) >> 8;
                int b1 = (int)(signed char)(r1 & 0xFF);
                int r2 = (r1 - b1) >> 8;
                int b2 = (int)(signed char)(r2 & 0xFF);
                int b3 = (r2 - b2) >> 8;             // |b3| <= 3
                int base = ((tu << 5) + tile)*A1STR + ci;
                Asm[base]      = (signed char)b0;
                Asm[base + 32] = (signed char)b1;
                Asm[base + 64] = (signed char)b2;
                Asm[base + 96] = (signed char)b3;
            }
        }
    }
    __syncthreads();

    unsigned Ab = (unsigned)__cvta_generic_to_shared(Asm);
    unsigned Ub = (unsigned)__cvta_generic_to_shared(smem + U1_OFF);
    int Mh = wid >> 2, nt = wid & 3;
    int apix  = (lid < 16) ? lid : (lid - 16);
    int akadd = (lid < 16) ? 0 : 16;
    int btu   = (lid >= 16) ? 1 : 0;
    int brow  = nt*8 + (lid & 7);
    int bkadd = ((lid >> 3) & 1) * 16;

    int S[16][4];
    int Y01[16];

    // ---- two passes: pass 0 -> planes (1,0) => S01 -> Y01 ; pass 1 -> (3,2)
    #pragma unroll
    for (int pass = 0; pass < 2; pass++) {
        int pHi = pass ? 3 : 1;
        int pLo = pass ? 2 : 0;
        #pragma unroll
        for (int tp = 0; tp < 8; tp++) {
            int tu0 = 2*tp;
            unsigned b0, b1, b2, b3;
            LDSM4(b0, b1, b2, b3, Ub + (unsigned)(((tu0 + btu)*32 + brow)*U1STR + bkadd));
            #pragma unroll
            for (int dtu = 0; dtu < 2; dtu++) {
                int tu = tu0 + dtu;
                unsigned bx = dtu ? b2 : b0, by = dtu ? b3 : b1;
                int* s = S[tu];
                s[0] = 0; s[1] = 0; s[2] = 0; s[3] = 0;
                unsigned a0, a1, a2, a3;
                LDSM4(a0, a1, a2, a3,
                      Ab + (unsigned)((tu*32 + Mh*16 + apix)*A1STR + pHi*32 + akadd));
                MMA_S8(s[0], s[1], s[2], s[3], a0, a1, a2, a3, bx, by);
                #pragma unroll
                for (int i = 0; i < 4; i++) s[i] = (int)((unsigned)s[i] << 8);
                LDSM4(a0, a1, a2, a3,
                      Ab + (unsigned)((tu*32 + Mh*16 + apix)*A1STR + pLo*32 + akadd));
                MMA_S8(s[0], s[1], s[2], s[3], a0, a1, a2, a3, bx, by);
            }
        }
        // transform S -> Y (AᵀMA), int32-safe
        #pragma unroll
        for (int sl = 0; sl < 4; sl++) {
            int g0[4], g1[4];
            #pragma unroll
            for (int uu = 0; uu < 4; uu++) {
                g0[uu] = S[uu][sl] + S[4+uu][sl] + S[8+uu][sl];
                g1[uu] = S[4+uu][sl] - S[8+uu][sl] - S[12+uu][sl];
            }
            int y0 = g0[0] + g0[1] + g0[2];
            int y1 = g0[1] - g0[2] - g0[3];
            int y2 = g1[0] + g1[1] + g1[2];
            int y3 = g1[1] - g1[2] - g1[3];
            if (pass == 0) {
                Y01[sl*4+0] = y0; Y01[sl*4+1] = y1;
                Y01[sl*4+2] = y2; Y01[sl*4+3] = y3;
            } else {
                // combine: Y = Y01 + Y23<<16 ; stash back into Y01 as int64 halves?
                // store Y23 into S row 0..3 slots (S now dead) for epilogue read
                S[0][sl] = y0; S[1][sl] = y1; S[2][sl] = y2; S[3][sl] = y3;
            }
        }
    }

    // epilogue: lane owns slots sl=half*2+cs -> (tile,co); Y in-lane
    int rowp = lid >> 2, colq = lid & 3;
    int coA = nt*8 + 2*colq;
    unsigned* mid = g_mid + (size_t)n*(CCH/4)*HWSZ;
    long long T0a = (long long)g_lut1_t0[coA],   Da = (long long)g_lut1_d[coA];
    long long T0b = (long long)g_lut1_t0[coA+1], Db = (long long)g_lut1_d[coA+1];
    #pragma unroll
    for (int half = 0; half < 2; half++) {
        int tile = Mh*16 + rowp + half*8;
        int slA = half*2, slB = half*2 + 1;
        int th_ = tile >> 3, tw_ = tile & 7;
        #pragma unroll
        for (int px = 0; px < 4; px++) {
            long long Ya = (long long)Y01[slA*4+px] + ((long long)S[px][slA] << 16);
            long long Yb = (long long)Y01[slB*4+px] + ((long long)S[px][slB] << 16);
            unsigned v = (unsigned)lut1_ll(Ya, T0a, Da)
                       | ((unsigned)lut1_ll(Yb, T0b, Db) << 8);
            unsigned o = __shfl_xor_sync(0xFFFFFFFFu, v, 1);
            if (!(colq & 1)) {
                int cig = nt*2 + (colq >> 1);
                int gh = h0 + 2*th_ + (px >> 1);
                int gw = w0 + 2*tw_ + (px & 1);
                mid[((size_t)cig*HH + gh)*WW + gw] = v | (o << 16);
            }
        }
    }
}

// ---------------------------------------------------------------------------
// Conv2 wino v2 (R14 verbatim, validated bit-exact)
// ---------------------------------------------------------------------------
#define A2STR 48
#define A2_BYTES (512*A2STR)
#define U2_OFF  A2_BYTES
#define CORR_OFF (U2_OFF + 512*A2STR)
#define SMEMW2  (CORR_OFF + 2048)

__global__ void __launch_bounds__(256, 2)
conv2_wino_kernel(float* __restrict__ out) {
    extern __shared__ __align__(16) char smem[];
    signed char* Asm = (signed char*)smem;
    unsigned* U32 = (unsigned*)(smem + U2_OFF);
    int* corrSm = (int*)(smem + CORR_OFF);

    int tid = threadIdx.x;
    int wid = tid >> 5, lid = tid & 31;
    int n  = blockIdx.z;
    int h0 = blockIdx.y * 8;
    int w0 = blockIdx.x * 16;

    for (int idx = tid; idx < 512*8; idx += 256) {
        int row = idx >> 3, c = idx & 7;
        U32[row*12 + c] = ((const unsigned*)g_u2)[idx];
    }
    for (int idx = tid; idx < 512; idx += 256) corrSm[idx] = g_c2corr[idx];

    {
        int cig = tid >> 5, tile = tid & 31;
        int th = tile >> 3, tw = tile & 7;
        const unsigned* mp = g_mid + ((size_t)n*(CCH/4) + cig)*HWSZ;
        unsigned dw[4][4];
        #pragma unroll
        for (int i = 0; i < 4; i++) {
            int gh = h0 + 2*th - 1 + i;
            bool okh = (gh >= 0 && gh < HH);
            #pragma unroll
            for (int j = 0; j < 4; j++) {
                int gw = w0 + 2*tw - 1 + j;
                dw[i][j] = (okh && gw >= 0 && gw < WW) ? mp[(size_t)gh*WW + gw] : 0u;
            }
        }
        const unsigned B8 = 0x08080808u, B16 = 0x10101010u, B32v = 0x20202020u;
        unsigned Tw[4][4];
        #pragma unroll
        for (int j = 0; j < 4; j++) {
            Tw[0][j] = (dw[0][j] + B8) - dw[2][j];
            Tw[1][j] =  dw[1][j] + dw[2][j] + B8;
            Tw[2][j] = (dw[2][j] + B8) - dw[1][j];
            Tw[3][j] = (dw[1][j] + B8) - dw[3][j];
        }
        #pragma unroll
        for (int r = 0; r < 4; r++) {
            unsigned Dp[4];
            Dp[0] = (Tw[r][0] + B32v) - Tw[r][2];
            Dp[1] =  Tw[r][1] + Tw[r][2] + B16;
            Dp[2] = (Tw[r][2] + B32v) - Tw[r][1];
            Dp[3] = (Tw[r][1] + B32v) - Tw[r][3];
            #pragma unroll
            for (int cc = 0; cc < 4; cc++) {
                int tu = r*4 + cc;
                *(unsigned*)(Asm + (tu*32 + tile)*A2STR + cig*4) = Dp[cc];
            }
        }
    }
    __syncthreads();

    unsigned Ab = (unsigned)__cvta_generic_to_shared(Asm);
    unsigned Ub = (unsigned)__cvta_generic_to_shared(smem + U2_OFF);
    int Mh = wid >> 2, nt = wid & 3;
    int apix  = (lid < 16) ? lid : (lid - 16);
    int akadd = (lid < 16) ? 0 : 16;
    int btu   = (lid >= 16) ? 1 : 0;
    int brow  = nt*8 + (lid & 7);
    int bkadd = ((lid >> 3) & 1) * 16;

    int S[16][4];
    #pragma unroll
    for (int tp = 0; tp < 8; tp++) {
        int tu0 = 2*tp;
        unsigned b0, b1, b2, b3;
        LDSM4(b0, b1, b2, b3, Ub + (unsigned)(((tu0 + btu)*32 + brow)*A2STR + bkadd));
        unsigned a0, a1, a2, a3;
        LDSM4(a0, a1, a2, a3, Ab + (unsigned)((tu0*32 + Mh*16 + apix)*A2STR + akadd));
        S[tu0][0] = 0; S[tu0][1] = 0; S[tu0][2] = 0; S[tu0][3] = 0;
        MMA_S8(S[tu0][0], S[tu0][1], S[tu0][2], S[tu0][3], a0, a1, a2, a3, b0, b1);
        LDSM4(a0, a1, a2, a3, Ab + (unsigned)(((tu0+1)*32 + Mh*16 + apix)*A2STR + akadd));
        S[tu0+1][0] = 0; S[tu0+1][1] = 0; S[tu0+1][2] = 0; S[tu0+1][3] = 0;
        MMA_S8(S[tu0+1][0], S[tu0+1][1], S[tu0+1][2], S[tu0+1][3], a0, a1, a2, a3, b2, b3);
    }

    int rowp = lid >> 2, colq = lid & 3;
    int coA = nt*8 + 2*colq;
    float* op = out + (size_t)n*CCH*HWSZ;
    #pragma unroll
    for (int sl = 0; sl < 4; sl++) {
        int tile = Mh*16 + rowp + ((sl >= 2) ? 8 : 0);
        int co   = coA + (sl & 1);
        const int* cp = corrSm + co*16;
        int M[16];
        #pragma unroll
        for (int tu = 0; tu < 16; tu++) M[tu] = S[tu][sl] - cp[tu];
        int g0[4], g1[4];
        #pragma unroll
        for (int uu = 0; uu < 4; uu++) {
            g0[uu] = M[uu] + M[4+uu] + M[8+uu];
            g1[uu] = M[4+uu] - M[8+uu] - M[12+uu];
        }
        int Y[4];
        Y[0] = g0[0] + g0[1] + g0[2];
        Y[1] = g0[1] - g0[2] - g0[3];
        Y[2] = g1[0] + g1[1] + g1[2];
        Y[3] = g1[1] - g1[2] - g1[3];
        int IT0 = g_lut2_t0[co], ID = g_lut2_d[co];
        int th_ = tile >> 3, tw_ = tile & 7;
        #pragma unroll
        for (int px = 0; px < 4; px++) {
            int lvl = 0;
            #pragma unroll
            for (int jj = 0; jj < 7; jj++) {
                int th2 = IT0 + jj * ID;
                lvl += (jj & 1) ? (Y[px] >= th2) : (Y[px] > th2);
            }
            int gh = h0 + 2*th_ + (px >> 1);
            int gw = w0 + 2*tw_ + (px & 1);
            op[((size_t)co*HH + gh)*WW + gw] = (float)lvl;
        }
    }
}

// ---------------------------------------------------------------------------
extern "C" void kernel_launch(void* const* d_in, const int* in_sizes, int n_in,
                              void* d_out, int out_size) {
    const float* x       = (const float*)d_in[0];
    const float* conv1_w = (const float*)d_in[1];
    const float* conv2_w = (const float*)d_in[2];
    const float* bn1_w   = (const float*)d_in[3];
    const float* bn1_b   = (const float*)d_in[4];
    const float* bn1_m   = (const float*)d_in[5];
    const float* bn1_v   = (const float*)d_in[6];
    const float* bn2_w   = (const float*)d_in[7];
    const float* bn2_b   = (const float*)d_in[8];
    const float* bn2_m   = (const float*)d_in[9];
    const float* bn2_v   = (const float*)d_in[10];
    const float* a1      = (const float*)d_in[11];
    const float* a2      = (const float*)d_in[12];
    const float* ns      = (const float*)d_in[13];

    setup_kernel<<<CCH, KELEMS>>>(conv1_w, conv2_w,
                                  bn1_w, bn1_b, bn1_m, bn1_v,
                                  bn2_w, bn2_b, bn2_m, bn2_v,
                                  a1, a2, ns);

    dim3 pgrid(HH, BB);
    prepass_kernel<<<pgrid, 256>>>(x);

    dim3 grid1(WW/16, HH/8, BB);
    cudaFuncSetAttribute(conv1_wino_kernel,
                         cudaFuncAttributeMaxDynamicSharedMemorySize, SMEMW1);
    conv1_wino_kernel<<<grid1, 256, SMEMW1>>>();

    cudaFuncSetAttribute(conv2_wino_kernel,
                         cudaFuncAttributeMaxDynamicSharedMemorySize, SMEMW2);
    conv2_wino_kernel<<<grid1, 256, SMEMW2>>>((float*)d_out);
}

// round 17
// speedup vs baseline: 2.3578x; 1.1593x over previous
#include <cuda_runtime.h>
#include <cstdint>

#define CCH 32
#define HH 224
#define WW 224
#define BB 16
#define KELEMS (CCH*9)
#define HWSZ (HH*WW)

__device__ signed char g_u1[16*CCH*CCH];
__device__ signed char g_u2[16*CCH*CCH];
__device__ long long g_lut1_th[CCH*8];   // ((t0+j*d)<<22) + (j even)
__device__ int  g_lut2_th[CCH*8];        // 4*(t0+j*d) + (j even)
__device__ int  g_c2yc[CCH*4];           // A^T C A per (co, px)
__device__ int  g_xt[(size_t)BB*HH*WW*32];
__device__ unsigned int g_mid[(size_t)BB*(CCH/4)*HH*WW];

#define LDSM4(r0,r1,r2,r3,addr)                                              \
    asm volatile("ldmatrix.sync.aligned.m8n8.x4.shared.b16 {%0,%1,%2,%3}, [%4];" \
        : "=r"(r0), "=r"(r1), "=r"(r2), "=r"(r3) : "r"(addr))

#define MMA_S8(c0,c1,c2,c3,a0,a1,a2,a3,b0,b1)                                \
    asm("mma.sync.aligned.m16n8k32.row.col.s32.s8.s8.s32 "                   \
        "{%0,%1,%2,%3}, {%4,%5,%6,%7}, {%8,%9}, {%0,%1,%2,%3};"              \
        : "+r"(c0), "+r"(c1), "+r"(c2), "+r"(c3)                             \
        : "r"(a0), "r"(a1), "r"(a2), "r"(a3), "r"(b0), "r"(b1))

// ---------------------------------------------------------------------------
__global__ void setup_kernel(const float* __restrict__ conv1_w,
                             const float* __restrict__ conv2_w,
                             const float* __restrict__ bn1_w, const float* __restrict__ bn1_b,
                             const float* __restrict__ bn1_m, const float* __restrict__ bn1_v,
                             const float* __restrict__ bn2_w, const float* __restrict__ bn2_b,
                             const float* __restrict__ bn2_m, const float* __restrict__ bn2_v,
                             const float* __restrict__ a1p, const float* __restrict__ a2p,
                             const float* __restrict__ nsp) {
    __shared__ float red[KELEMS];
    __shared__ float mean1s, mean2s;
    __shared__ int   ssm1[KELEMS], ssm2[KELEMS];
    __shared__ int   Us[CCH][16];
    int co = blockIdx.x;
    int t  = threadIdx.x;           // 288

    float v1 = conv1_w[co*KELEMS + t];
    float v2 = conv2_w[co*KELEMS + t];

    red[t] = v1; __syncthreads();
    if (t < 32) red[t] += red[t + 256];
    __syncthreads();
    for (int s = 128; s > 0; s >>= 1) { if (t < s) red[t] += red[t + s]; __syncthreads(); }
    if (t == 0) mean1s = red[0] * (1.f / 288.f);
    __syncthreads();
    float m1 = mean1s;
    __syncthreads();

    red[t] = v2; __syncthreads();
    if (t < 32) red[t] += red[t + 256];
    __syncthreads();
    for (int s = 128; s > 0; s >>= 1) { if (t < s) red[t] += red[t + s]; __syncthreads(); }
    if (t == 0) mean2s = red[0] * (1.f / 288.f);
    __syncthreads();
    float m2 = mean2s;

    float d1 = v1 - m1;
    ssm1[t] = (d1 > 0.f) ? 1 : ((d1 < 0.f) ? -1 : 0);
    float d2 = v2 - m2;
    ssm2[t] = (d2 > 0.f) ? 1 : ((d2 < 0.f) ? -1 : 0);
    __syncthreads();

    if (t < CCH) {   // ci = t: Winograd U = (2G) w (2G)^T for BOTH convs
        #pragma unroll
        for (int which = 0; which < 2; which++) {
            const int* sv = which ? ssm2 : ssm1;
            signed char* gu = which ? g_u2 : g_u1;
            int w3[3][3];
            #pragma unroll
            for (int kh = 0; kh < 3; kh++)
                #pragma unroll
                for (int kw = 0; kw < 3; kw++)
                    w3[kh][kw] = sv[t*9 + kh*3 + kw];
            int T[4][3];
            #pragma unroll
            for (int j = 0; j < 3; j++) {
                T[0][j] = 2*w3[0][j];
                T[1][j] = w3[0][j] + w3[1][j] + w3[2][j];
                T[2][j] = w3[0][j] - w3[1][j] + w3[2][j];
                T[3][j] = 2*w3[2][j];
            }
            #pragma unroll
            for (int r = 0; r < 4; r++) {
                int u0 = 2*T[r][0];
                int u1 = T[r][0] + T[r][1] + T[r][2];
                int u2 = T[r][0] - T[r][1] + T[r][2];
                int u3 = 2*T[r][2];
                gu[((r*4+0)*CCH + co)*CCH + t] = (signed char)u0;
                gu[((r*4+1)*CCH + co)*CCH + t] = (signed char)u1;
                gu[((r*4+2)*CCH + co)*CCH + t] = (signed char)u2;
                gu[((r*4+3)*CCH + co)*CCH + t] = (signed char)u3;
                if (which) {
                    Us[t][r*4+0] = u0; Us[t][r*4+1] = u1;
                    Us[t][r*4+2] = u2; Us[t][r*4+3] = u3;
                }
            }
        }
    }
    __syncthreads();

    if (t == 0) {
        // conv2 bias corrections folded to output domain: YC = A^T C A
        int C[16];
        #pragma unroll
        for (int tu = 0; tu < 16; tu++) {
            int s = 0;
            for (int c2 = 0; c2 < CCH; c2++) s += Us[c2][tu];
            C[tu] = 32 * s;
        }
        const int A0[4] = {1,1,1,0}, A1r[4] = {0,1,-1,-1};
        #pragma unroll
        for (int px = 0; px < 4; px++) {
            int pr = px >> 1, pc = px & 1;
            int acc = 0;
            for (int r = 0; r < 4; r++)
                for (int c = 0; c < 4; c++) {
                    int cr = pr ? A1r[r] : A0[r];
                    int cc = pc ? A1r[c] : A0[c];
                    acc += cr * cc * C[r*4 + c];
                }
            g_c2yc[co*4 + px] = acc;
        }

        float a1 = *a1p, a2 = *a2p, ns = *nsp;
        {
            float std = sqrtf(bn1_v[co] + 1e-5f);
            float w = bn1_w[co] / std;
            float b = bn1_b[co] - w * bn1_m[co];
            float den = a1 * w;
            int t01 = (int)rintf((0.5f * a2 - b) / den);
            int t11 = (int)rintf((1.5f * a2 - b) / den);
            int dd = t11 - t01;
            #pragma unroll
            for (int j = 0; j < 7; j++)
                g_lut1_th[co*8 + j] = (((long long)(t01 + j*dd)) << 22)
                                    + ((j & 1) ? 0 : 1);
        }
        {
            float std = sqrtf(bn2_v[co] + 1e-5f);
            float w = bn2_w[co] / std;
            float b = bn2_b[co] - w * bn2_m[co];
            float den = a2 * w;
            int t02 = (int)rintf((0.5f * ns - b) / den);
            int t12 = (int)rintf((1.5f * ns - b) / den);
            int dd = t12 - t02;
            #pragma unroll
            for (int j = 0; j < 7; j++)
                g_lut2_th[co*8 + j] = 4*(t02 + j*dd) + ((j & 1) ? 0 : 1);
        }
    }
}

// ---------------------------------------------------------------------------
__global__ void __launch_bounds__(256)
prepass_kernel(const float* __restrict__ x) {
    __shared__ int stage[WW*33];
    int n = blockIdx.y, h = blockIdx.x;
    int tid = threadIdx.x;
    for (int idx = tid; idx < CCH*WW; idx += 256) {
        int ci = idx / WW, w = idx % WW;
        float v = x[(((size_t)n*CCH + ci)*HH + h)*WW + w];
        stage[w*33 + ci] = __float2int_rn(v * 1048576.f);   // 2^20
    }
    __syncthreads();
    int* dst = g_xt + ((size_t)n*HH + h)*WW*32;
    for (int idx = tid; idx < WW*32; idx += 256) {
        int w = idx >> 5, ci = idx & 31;
        dst[idx] = stage[w*33 + ci];
    }
}

// ---------------------------------------------------------------------------
// Conv1 Winograd @2^20, 4 digit planes. B-frags via direct LDG from g_u1
// (smem = A only -> 3 CTAs/SM). Streaming int64 Y accumulation per tu.
// ---------------------------------------------------------------------------
#define A1STR 144
#define SMEMW1 (512*A1STR)              // 73728

__global__ void __launch_bounds__(256, 3)
conv1_wino_kernel() {
    extern __shared__ __align__(16) char smem[];
    signed char* Asm = (signed char*)smem;

    int tid = threadIdx.x;
    int wid = tid >> 5, lid = tid & 31;
    int n  = blockIdx.z;
    int h0 = blockIdx.y * 8;
    int w0 = blockIdx.x * 16;

    const int* xin = g_xt + (size_t)n*HWSZ*32;
    #pragma unroll
    for (int k = 0; k < 4; k++) {
        int u = tid + 256*k;
        int tile = u >> 5, ci = u & 31;
        int th = tile >> 3, tw = tile & 7;
        int d[4][4];
        #pragma unroll
        for (int i = 0; i < 4; i++) {
            int gh = h0 + 2*th - 1 + i;
            bool okh = (gh >= 0 && gh < HH);
            int ghc = okh ? gh : 0;
            #pragma unroll
            for (int j = 0; j < 4; j++) {
                int gw = w0 + 2*tw - 1 + j;
                bool ok = okh && (gw >= 0 && gw < WW);
                int gwc = ok ? gw : 0;
                int v = xin[((size_t)ghc*WW + gwc)*32 + ci];
                d[i][j] = ok ? v : 0;
            }
        }
        int T[4][4];
        #pragma unroll
        for (int j = 0; j < 4; j++) {
            T[0][j] = d[0][j] - d[2][j];
            T[1][j] = d[1][j] + d[2][j];
            T[2][j] = d[2][j] - d[1][j];
            T[3][j] = d[1][j] - d[3][j];
        }
        #pragma unroll
        for (int i = 0; i < 4; i++) {
            int Dv[4];
            Dv[0] = T[i][0] - T[i][2];
            Dv[1] = T[i][1] + T[i][2];
            Dv[2] = T[i][2] - T[i][1];
            Dv[3] = T[i][1] - T[i][3];
            #pragma unroll
            for (int uu = 0; uu < 4; uu++) {
                int tu = i*4 + uu;
                int v = Dv[uu];
                int b0 = (int)(signed char)(v & 0xFF);
                int r1 = (v - b0) >> 8;
                int b1 = (int)(signed char)(r1 & 0xFF);
                int r2 = (r1 - b1) >> 8;
                int b2 = (int)(signed char)(r2 & 0xFF);
                int b3 = (r2 - b2) >> 8;
                int base = ((tu << 5) + tile)*A1STR + ci;
                Asm[base]      = (signed char)b0;
                Asm[base + 32] = (signed char)b1;
                Asm[base + 64] = (signed char)b2;
                Asm[base + 96] = (signed char)b3;
            }
        }
    }
    __syncthreads();

    unsigned Ab = (unsigned)__cvta_generic_to_shared(Asm);
    int Mh = wid >> 2, nt = wid & 3;
    int apix  = (lid < 16) ? lid : (lid - 16);
    int akadd = (lid < 16) ? 0 : 16;
    // direct-LDG B fragment base: row = nt*8 + lid/4, bytes (lid%4)*4 (+16 hi)
    const char* ubase = (const char*)g_u1 + (nt*8 + (lid >> 2))*32 + (lid & 3)*4;

    long long Y64[16];
    #pragma unroll
    for (int i = 0; i < 16; i++) Y64[i] = 0;

    #pragma unroll
    for (int tu = 0; tu < 16; tu++) {
        unsigned b0 = *(const unsigned*)(ubase + tu*1024);
        unsigned b1 = *(const unsigned*)(ubase + tu*1024 + 16);
        unsigned abase = Ab + (unsigned)((tu*32 + Mh*16 + apix)*A1STR + akadd);
        unsigned a0, a1, a2, a3;
        int s0[4] = {0,0,0,0};
        LDSM4(a0, a1, a2, a3, abase + 32);            // plane 1
        MMA_S8(s0[0], s0[1], s0[2], s0[3], a0, a1, a2, a3, b0, b1);
        #pragma unroll
        for (int i = 0; i < 4; i++) s0[i] = (int)((unsigned)s0[i] << 8);
        LDSM4(a0, a1, a2, a3, abase);                 // plane 0
        MMA_S8(s0[0], s0[1], s0[2], s0[3], a0, a1, a2, a3, b0, b1);
        int s1[4] = {0,0,0,0};
        LDSM4(a0, a1, a2, a3, abase + 96);            // plane 3
        MMA_S8(s1[0], s1[1], s1[2], s1[3], a0, a1, a2, a3, b0, b1);
        #pragma unroll
        for (int i = 0; i < 4; i++) s1[i] = (int)((unsigned)s1[i] << 8);
        LDSM4(a0, a1, a2, a3, abase + 64);            // plane 2
        MMA_S8(s1[0], s1[1], s1[2], s1[3], a0, a1, a2, a3, b0, b1);

        const int r = tu >> 2, c = tu & 3;            // compile-time per unroll
        #pragma unroll
        for (int sl = 0; sl < 4; sl++) {
            long long M = (long long)s0[sl] + ((long long)s1[sl] << 16);
            if (r < 3 && c < 3) Y64[sl*4 + 0] += M;
            if (r < 3) {
                if (c == 1) Y64[sl*4 + 1] += M;
                else if (c >= 2) Y64[sl*4 + 1] -= M;
            }
            if (c < 3) {
                if (r == 1) Y64[sl*4 + 2] += M;
                else if (r >= 2) Y64[sl*4 + 2] -= M;
            }
            if (r > 0 && c > 0) {
                int sg = ((r == 1) ? 1 : -1) * ((c == 1) ? 1 : -1);
                if (sg > 0) Y64[sl*4 + 3] += M; else Y64[sl*4 + 3] -= M;
            }
        }
    }

    // epilogue: table-LUT (uniform >=), pack via shfl pair
    int rowp = lid >> 2, colq = lid & 3;
    int coA = nt*8 + 2*colq;
    const long long* thA = g_lut1_th + coA*8;
    const long long* thB = thA + 8;
    unsigned* mid = g_mid + (size_t)n*(CCH/4)*HWSZ;
    #pragma unroll
    for (int half = 0; half < 2; half++) {
        int tile = Mh*16 + rowp + half*8;
        int slA = half*2, slB = half*2 + 1;
        int th_ = tile >> 3, tw_ = tile & 7;
        #pragma unroll
        for (int px = 0; px < 4; px++) {
            long long Ya = Y64[slA*4 + px], Yb = Y64[slB*4 + px];
            int la = 0, lb = 0;
            #pragma unroll
            for (int jj = 0; jj < 7; jj++) {
                la += (Ya >= thA[jj]);
                lb += (Yb >= thB[jj]);
            }
            unsigned v = (unsigned)la | ((unsigned)lb << 8);
            unsigned o = __shfl_xor_sync(0xFFFFFFFFu, v, 1);
            if (!(colq & 1)) {
                int cig = nt*2 + (colq >> 1);
                int gh = h0 + 2*th_ + (px >> 1);
                int gw = w0 + 2*tw_ + (px & 1);
                mid[((size_t)cig*HH + gh)*WW + gw] = v | (o << 16);
            }
        }
    }
}

// ---------------------------------------------------------------------------
// Conv2 wino (R14 fabric): corr folded into YC offsets; table LUT.
// ---------------------------------------------------------------------------
#define A2STR 48
#define A2_BYTES (512*A2STR)
#define U2_OFF  A2_BYTES
#define SMEMW2  (U2_OFF + 512*A2STR)    // 49152

__global__ void __launch_bounds__(256, 2)
conv2_wino_kernel(float* __restrict__ out) {
    extern __shared__ __align__(16) char smem[];
    signed char* Asm = (signed char*)smem;
    unsigned* U32 = (unsigned*)(smem + U2_OFF);

    int tid = threadIdx.x;
    int wid = tid >> 5, lid = tid & 31;
    int n  = blockIdx.z;
    int h0 = blockIdx.y * 8;
    int w0 = blockIdx.x * 16;

    for (int idx = tid; idx < 512*8; idx += 256) {
        int row = idx >> 3, c = idx & 7;
        U32[row*12 + c] = ((const unsigned*)g_u2)[idx];
    }

    {
        int cig = tid >> 5, tile = tid & 31;
        int th = tile >> 3, tw = tile & 7;
        const unsigned* mp = g_mid + ((size_t)n*(CCH/4) + cig)*HWSZ;
        unsigned dw[4][4];
        #pragma unroll
        for (int i = 0; i < 4; i++) {
            int gh = h0 + 2*th - 1 + i;
            bool okh = (gh >= 0 && gh < HH);
            #pragma unroll
            for (int j = 0; j < 4; j++) {
                int gw = w0 + 2*tw - 1 + j;
                dw[i][j] = (okh && gw >= 0 && gw < WW) ? mp[(size_t)gh*WW + gw] : 0u;
            }
        }
        const unsigned B8 = 0x08080808u, B16 = 0x10101010u, B32v = 0x20202020u;
        unsigned Tw[4][4];
        #pragma unroll
        for (int j = 0; j < 4; j++) {
            Tw[0][j] = (dw[0][j] + B8) - dw[2][j];
            Tw[1][j] =  dw[1][j] + dw[2][j] + B8;
            Tw[2][j] = (dw[2][j] + B8) - dw[1][j];
            Tw[3][j] = (dw[1][j] + B8) - dw[3][j];
        }
        #pragma unroll
        for (int r = 0; r < 4; r++) {
            unsigned Dp[4];
            Dp[0] = (Tw[r][0] + B32v) - Tw[r][2];
            Dp[1] =  Tw[r][1] + Tw[r][2] + B16;
            Dp[2] = (Tw[r][2] + B32v) - Tw[r][1];
            Dp[3] = (Tw[r][1] + B32v) - Tw[r][3];
            #pragma unroll
            for (int cc = 0; cc < 4; cc++) {
                int tu = r*4 + cc;
                *(unsigned*)(Asm + (tu*32 + tile)*A2STR + cig*4) = Dp[cc];
            }
        }
    }
    __syncthreads();

    unsigned Ab = (unsigned)__cvta_generic_to_shared(Asm);
    unsigned Ub = (unsigned)__cvta_generic_to_shared(smem + U2_OFF);
    int Mh = wid >> 2, nt = wid & 3;
    int apix  = (lid < 16) ? lid : (lid - 16);
    int akadd = (lid < 16) ? 0 : 16;
    int btu   = (lid >= 16) ? 1 : 0;
    int brow  = nt*8 + (lid & 7);
    int bkadd = ((lid >> 3) & 1) * 16;

    int S[16][4];
    #pragma unroll
    for (int tp = 0; tp < 8; tp++) {
        int tu0 = 2*tp;
        unsigned b0, b1, b2, b3;
        LDSM4(b0, b1, b2, b3, Ub + (unsigned)(((tu0 + btu)*32 + brow)*A2STR + bkadd));
        unsigned a0, a1, a2, a3;
        LDSM4(a0, a1, a2, a3, Ab + (unsigned)((tu0*32 + Mh*16 + apix)*A2STR + akadd));
        S[tu0][0] = 0; S[tu0][1] = 0; S[tu0][2] = 0; S[tu0][3] = 0;
        MMA_S8(S[tu0][0], S[tu0][1], S[tu0][2], S[tu0][3], a0, a1, a2, a3, b0, b1);
        LDSM4(a0, a1, a2, a3, Ab + (unsigned)(((tu0+1)*32 + Mh*16 + apix)*A2STR + akadd));
        S[tu0+1][0] = 0; S[tu0+1][1] = 0; S[tu0+1][2] = 0; S[tu0+1][3] = 0;
        MMA_S8(S[tu0+1][0], S[tu0+1][1], S[tu0+1][2], S[tu0+1][3], a0, a1, a2, a3, b2, b3);
    }

    int rowp = lid >> 2, colq = lid & 3;
    int coA = nt*8 + 2*colq;
    float* op = out + (size_t)n*CCH*HWSZ;
    #pragma unroll
    for (int sl = 0; sl < 4; sl++) {
        int tile = Mh*16 + rowp + ((sl >= 2) ? 8 : 0);
        int co   = coA + (sl & 1);
        const int* thp = g_lut2_th + co*8;
        const int* ycp = g_c2yc + co*4;
        int g0[4], g1[4];
        #pragma unroll
        for (int uu = 0; uu < 4; uu++) {
            g0[uu] = S[uu][sl] + S[4+uu][sl] + S[8+uu][sl];
            g1[uu] = S[4+uu][sl] - S[8+uu][sl] - S[12+uu][sl];
        }
        int Y[4];
        Y[0] = g0[0] + g0[1] + g0[2];
        Y[1] = g0[1] - g0[2] - g0[3];
        Y[2] = g1[0] + g1[1] + g1[2];
        Y[3] = g1[1] - g1[2] - g1[3];
        int th_ = tile >> 3, tw_ = tile & 7;
        #pragma unroll
        for (int px = 0; px < 4; px++) {
            int Z = Y[px] - ycp[px];
            int lvl = 0;
            #pragma unroll
            for (int jj = 0; jj < 7; jj++) lvl += (Z >= thp[jj]);
            int gh = h0 + 2*th_ + (px >> 1);
            int gw = w0 + 2*tw_ + (px & 1);
            op[((size_t)co*HH + gh)*WW + gw] = (float)lvl;
        }
    }
}

// ---------------------------------------------------------------------------
extern "C" void kernel_launch(void* const* d_in, const int* in_sizes, int n_in,
                              void* d_out, int out_size) {
    const float* x       = (const float*)d_in[0];
    const float* conv1_w = (const float*)d_in[1];
    const float* conv2_w = (const float*)d_in[2];
    const float* bn1_w   = (const float*)d_in[3];
    const float* bn1_b   = (const float*)d_in[4];
    const float* bn1_m   = (const float*)d_in[5];
    const float* bn1_v   = (const float*)d_in[6];
    const float* bn2_w   = (const float*)d_in[7];
    const float* bn2_b   = (const float*)d_in[8];
    const float* bn2_m   = (const float*)d_in[9];
    const float* bn2_v   = (const float*)d_in[10];
    const float* a1      = (const float*)d_in[11];
    const float* a2      = (const float*)d_in[12];
    const float* ns      = (const float*)d_in[13];

    setup_kernel<<<CCH, KELEMS>>>(conv1_w, conv2_w,
                                  bn1_w, bn1_b, bn1_m, bn1_v,
                                  bn2_w, bn2_b, bn2_m, bn2_v,
                                  a1, a2, ns);

    dim3 pgrid(HH, BB);
    prepass_kernel<<<pgrid, 256>>>(x);

    dim3 grid1(WW/16, HH/8, BB);
    cudaFuncSetAttribute(conv1_wino_kernel,
                         cudaFuncAttributeMaxDynamicSharedMemorySize, SMEMW1);
    conv1_wino_kernel<<<grid1, 256, SMEMW1>>>();

    cudaFuncSetAttribute(conv2_wino_kernel,
                         cudaFuncAttributeMaxDynamicSharedMemorySize, SMEMW2);
    conv2_wino_kernel<<<grid1, 256, SMEMW2>>>((float*)d_out);
}